// round 5
// baseline (speedup 1.0000x reference)
#include <cuda_runtime.h>

#define BN 8
#define SN 2048
#define EN 8
#define NTOK (BN*SN)
#define KSPLIT 16
#define KCHUNK (SN/KSPLIT)   /* 128 keys per CTA chunk */
#define NTHR 256             /* 8 warps; each warp owns 16 queries */
#define QPC 128              /* queries per CTA */
#define LOG2E 1.4426950408889634f

typedef unsigned long long u64;

/* Scratch (allocation-free rule: device globals) */
__device__ float g_Qf[(size_t)NTOK * 16];   /* [tok][16] tf32-rounded, *log2e */
__device__ float g_Kf[(size_t)NTOK * 16];   /* [tok][16] tf32-rounded */
__device__ float g_V [(size_t)NTOK * 8];    /* pair-interleaved [tok/2][comp][2], fp32 */
__device__ float g_den[(size_t)NTOK * KSPLIT];
__device__ float g_num[(size_t)NTOK * KSPLIT * 8];

/* ---- packed f32x2 helpers (Blackwell FFMA2 via PTX) ---- */
__device__ __forceinline__ u64 fma2(u64 a, u64 b, u64 c) {
    u64 d;
    asm("fma.rn.f32x2 %0, %1, %2, %3;" : "=l"(d) : "l"(a), "l"(b), "l"(c));
    return d;
}
__device__ __forceinline__ u64 add2(u64 a, u64 b) {
    u64 d;
    asm("add.rn.f32x2 %0, %1, %2;" : "=l"(d) : "l"(a), "l"(b));
    return d;
}
__device__ __forceinline__ float2 unpack2(u64 d) {
    float2 r;
    asm("mov.b64 {%0, %1}, %2;" : "=f"(r.x), "=f"(r.y) : "l"(d));
    return r;
}
__device__ __forceinline__ u64 pack2(float lo, float hi) {
    u64 d;
    asm("mov.b64 %0, {%1, %2};" : "=l"(d) : "f"(lo), "f"(hi));
    return d;
}
__device__ __forceinline__ float ex2(float x) {
    float y;
    asm("ex2.approx.ftz.f32 %0, %1;" : "=f"(y) : "f"(x));
    return y;
}
__device__ __forceinline__ float tf32r(float x) {
    unsigned int u;
    asm("cvt.rna.tf32.f32 %0, %1;" : "=r"(u) : "f"(x));
    return __uint_as_float(u);
}
__device__ __forceinline__ u64 shfl64(u64 v, int m) {
    return __shfl_xor_sync(0xffffffffu, v, m);
}

/* tf32 m16n8k8 MMA: D += A*B, A 16x8 (features), B 8x8 (feat x keys) */
__device__ __forceinline__ void mma_tf32(float c[4], const unsigned int a[4],
                                         unsigned int b0, unsigned int b1) {
    asm("mma.sync.aligned.m16n8k8.row.col.f32.tf32.tf32.f32 "
        "{%0,%1,%2,%3}, {%4,%5,%6,%7}, {%8,%9}, {%0,%1,%2,%3};"
        : "+f"(c[0]), "+f"(c[1]), "+f"(c[2]), "+f"(c[3])
        : "r"(a[0]), "r"(a[1]), "r"(a[2]), "r"(a[3]), "r"(b0), "r"(b1));
}

/* ---------------- Kernel 1: per-token features ----------------
 * blockIdx.y = {0:Q, 1:K, 2:V}.
 * qlayer(x, phi)_w = prod_{u<=w} cos(x_u+phi_u)  (w>=1),
 * qlayer_0 = prod_{u=1..7} cos(x_u+phi_u).
 * 16-dim unit-norm features Phi so sim = Phi_q . Phi_k.
 */
__device__ __forceinline__ void qk_features16(const float xv[8], const float* __restrict__ ph,
                                              float F[16]) {
    float c[8];
#pragma unroll
    for (int u = 0; u < 8; u++) c[u] = __cosf(xv[u] + __ldg(&ph[u]));
    float q1 = c[0] * c[1];
    float q2 = q1 * c[2];
    float q3 = q2 * c[3];
    float q0 = c[1] * c[2] * c[3] * c[4] * c[5] * c[6] * c[7];
    float s0, s1, s2, s3, a0, a1, a2, a3;
    __sincosf(0.5f * q0, &s0, &a0);
    __sincosf(0.5f * q1, &s1, &a1);
    __sincosf(0.5f * q2, &s2, &a2);
    __sincosf(0.5f * q3, &s3, &a3);
    float t01[4] = {a0 * a1, s0 * a1, a0 * s1, s0 * s1};
    float t23[4] = {a2 * a3, s2 * a3, a2 * s3, s2 * s3};
#pragma unroll
    for (int m = 0; m < 16; m++) F[m] = t01[m & 3] * t23[m >> 2];
}

__global__ void features_kernel(const float* __restrict__ x,
                                const float* __restrict__ phi_q,
                                const float* __restrict__ phi_k,
                                const float* __restrict__ phi_v) {
    int t = blockIdx.x * blockDim.x + threadIdx.x;
    if (t >= NTOK) return;
    const int kind = blockIdx.y;

    float xv[8];
    const float4* xp = reinterpret_cast<const float4*>(x + (size_t)t * 8);
    float4 xa = xp[0], xb = xp[1];
    xv[0] = xa.x; xv[1] = xa.y; xv[2] = xa.z; xv[3] = xa.w;
    xv[4] = xb.x; xv[5] = xb.y; xv[6] = xb.z; xv[7] = xb.w;

    if (kind == 0) {
        float F[16];
        qk_features16(xv, phi_q, F);
        float4* qo = reinterpret_cast<float4*>(g_Qf + (size_t)t * 16);
#pragma unroll
        for (int i = 0; i < 4; i++)
            qo[i] = make_float4(tf32r(F[4*i] * LOG2E), tf32r(F[4*i+1] * LOG2E),
                                tf32r(F[4*i+2] * LOG2E), tf32r(F[4*i+3] * LOG2E));
    } else if (kind == 1) {
        float F[16];
        qk_features16(xv, phi_k, F);
        float4* ko = reinterpret_cast<float4*>(g_Kf + (size_t)t * 16);
#pragma unroll
        for (int i = 0; i < 4; i++)
            ko[i] = make_float4(tf32r(F[4*i]), tf32r(F[4*i+1]),
                                tf32r(F[4*i+2]), tf32r(F[4*i+3]));
    } else {
        float c[8];
#pragma unroll
        for (int u = 0; u < 8; u++) c[u] = __cosf(xv[u] + __ldg(&phi_v[u]));
        float v[8];
        v[1] = c[0] * c[1];
#pragma unroll
        for (int w = 2; w < 8; w++) v[w] = v[w - 1] * c[w];
        v[0] = c[1] * c[2] * c[3] * c[4] * c[5] * c[6] * c[7];
        float* vo = g_V + (size_t)(t & ~1) * 8 + (t & 1);
#pragma unroll
        for (int ccc = 0; ccc < 8; ccc++) vo[ccc * 2] = v[ccc];
    }
}

/* ---------------- Kernel 2: fused attention partials ----------------
 * QK^T via tf32 mma.sync (tensor pipe), exp + PV scalar packed f32x2.
 * Warp = 16 queries x 128 keys. CTA = 8 warps = 128 queries.
 * C-fragment cols (2*t4, 2*t4+1) = adjacent keys -> pair-packed V acc.
 */
__global__ __launch_bounds__(NTHR) void attn_partial_kernel() {
    __shared__ unsigned int sK[KCHUNK * 16];   /* 8KB, XOR-swizzled features */
    __shared__ u64 sV[KCHUNK / 2 * 8];         /* 4KB, chunk-swizzled */

    const int b  = blockIdx.z;
    const int ks = blockIdx.y;
    const int tid = threadIdx.x;
    const int warp = tid >> 5, lane = tid & 31;
    const int g = lane >> 2, t4 = lane & 3;
    const int kbase = b * SN + ks * KCHUNK;

    /* fill smem with swizzles */
    {
        const float4* kg = reinterpret_cast<const float4*>(g_Kf + (size_t)kbase * 16);
        float4* s4 = reinterpret_cast<float4*>(sK);
#pragma unroll
        for (int i = tid; i < KCHUNK * 4; i += NTHR) {
            int k = i >> 2, j = i & 3;
            s4[(k << 2) | (j ^ ((k >> 1) & 3))] = kg[i];
        }
        const ulonglong2* vg2 = reinterpret_cast<const ulonglong2*>(g_V + (size_t)kbase * 8);
        ulonglong2* sv2 = reinterpret_cast<ulonglong2*>(sV);
        {
            int p = tid >> 2, m = tid & 3;
            sv2[(p << 2) | (m ^ (p & 3))] = vg2[tid];
        }
    }

    /* A fragments: 16 queries, K=16 features, 2 k-steps */
    const int q0 = blockIdx.x * QPC + warp * 16;
    unsigned int a[2][4];
    {
        const float* Q = g_Qf + (size_t)(b * SN + q0) * 16;
#pragma unroll
        for (int ksp = 0; ksp < 2; ksp++)
#pragma unroll
            for (int i = 0; i < 4; i++)
                a[ksp][i] = __float_as_uint(
                    Q[(size_t)(g + 8 * (i & 1)) * 16 + t4 + 4 * (i >> 1) + 8 * ksp]);
    }

    u64 acc[2][8];
    u64 den[2];
#pragma unroll
    for (int h = 0; h < 2; h++) {
        den[h] = 0ull;
#pragma unroll
        for (int c = 0; c < 8; c++) acc[h][c] = 0ull;
    }

    __syncthreads();

    const unsigned int sw4 = ((g >> 1) & 3) << 2;
    const ulonglong2* sv2 = reinterpret_cast<const ulonglong2*>(sV);

#pragma unroll 4
    for (int k0 = 0; k0 < KCHUNK; k0 += 8) {
        /* B fragments: feature (t4+4j+8ksp) of key (k0+g), swizzled */
        const unsigned int* kr = sK + (size_t)(k0 + g) * 16;
        unsigned int b00 = kr[(t4 + 0) ^ sw4];
        unsigned int b01 = kr[(t4 + 4) ^ sw4];
        unsigned int b10 = kr[(t4 + 8) ^ sw4];
        unsigned int b11 = kr[(t4 + 12) ^ sw4];

        float c[4] = {0.f, 0.f, 0.f, 0.f};
        mma_tf32(c, a[0], b00, b01);
        mma_tf32(c, a[1], b10, b11);

        /* c[0],c[1]: row g, keys k0+2t4, k0+2t4+1; c[2],c[3]: row g+8 */
        u64 ep0 = pack2(ex2(fabsf(c[0])), ex2(fabsf(c[1])));
        u64 ep1 = pack2(ex2(fabsf(c[2])), ex2(fabsf(c[3])));
        den[0] = add2(den[0], ep0);
        den[1] = add2(den[1], ep1);

        int p = (k0 >> 1) + t4;
#pragma unroll
        for (int m = 0; m < 4; m++) {
            ulonglong2 vv = sv2[(p << 2) | (m ^ t4)];   /* comps 2m, 2m+1 */
            acc[0][2 * m]     = fma2(ep0, vv.x, acc[0][2 * m]);
            acc[0][2 * m + 1] = fma2(ep0, vv.y, acc[0][2 * m + 1]);
            acc[1][2 * m]     = fma2(ep1, vv.x, acc[1][2 * m]);
            acc[1][2 * m + 1] = fma2(ep1, vv.y, acc[1][2 * m + 1]);
        }
    }

    /* reduce across the 4 t4-lanes sharing each query row */
#pragma unroll
    for (int h = 0; h < 2; h++) {
        den[h] = add2(den[h], shfl64(den[h], 1));
        den[h] = add2(den[h], shfl64(den[h], 2));
#pragma unroll
        for (int c = 0; c < 8; c++) {
            acc[h][c] = add2(acc[h][c], shfl64(acc[h][c], 1));
            acc[h][c] = add2(acc[h][c], shfl64(acc[h][c], 2));
        }
    }

    if (t4 == 0) {
#pragma unroll
        for (int h = 0; h < 2; h++) {
            int q = q0 + g + 8 * h;
            float2 d = unpack2(den[h]);
            g_den[(size_t)(b * SN + q) * KSPLIT + ks] = d.x + d.y;
            float n[8];
#pragma unroll
            for (int c = 0; c < 8; c++) {
                float2 u = unpack2(acc[h][c]);
                n[c] = u.x + u.y;
            }
            float4* o = reinterpret_cast<float4*>(g_num + ((size_t)(b * SN + q) * KSPLIT + ks) * 8);
            o[0] = make_float4(n[0], n[1], n[2], n[3]);
            o[1] = make_float4(n[4], n[5], n[6], n[7]);
        }
    }
}

/* ---------------- Kernel 3: combine splits + output projection ---------------- */
__global__ void finalize_kernel(const float* __restrict__ W,
                                const float* __restrict__ bias,
                                float* __restrict__ out) {
    int t = blockIdx.x * blockDim.x + threadIdx.x;
    if (t >= NTOK) return;

    float den = 0.f, num[8];
#pragma unroll
    for (int e = 0; e < 8; e++) num[e] = 0.f;
#pragma unroll
    for (int ks = 0; ks < KSPLIT; ks++) {
        den += g_den[(size_t)t * KSPLIT + ks];
        const float4* p = reinterpret_cast<const float4*>(g_num + ((size_t)t * KSPLIT + ks) * 8);
        float4 p0 = p[0], p1 = p[1];
        num[0] += p0.x; num[1] += p0.y; num[2] += p0.z; num[3] += p0.w;
        num[4] += p1.x; num[5] += p1.y; num[6] += p1.z; num[7] += p1.w;
    }
    float inv = 1.0f / den;
    float o[8];
#pragma unroll
    for (int e = 0; e < 8; e++) o[e] = num[e] * inv;

#pragma unroll
    for (int d = 0; d < 8; d++) {
        float y = __ldg(&bias[d]);
#pragma unroll
        for (int e = 0; e < 8; e++) y += o[e] * __ldg(&W[d * 8 + e]);
        out[t * 8 + d] = y;
    }
}

extern "C" void kernel_launch(void* const* d_in, const int* in_sizes, int n_in,
                              void* d_out, int out_size) {
    const float* x     = (const float*)d_in[0];
    const float* phi_q = (const float*)d_in[1];
    const float* phi_k = (const float*)d_in[2];
    const float* phi_v = (const float*)d_in[3];
    const float* W     = (const float*)d_in[4];
    const float* bias  = (const float*)d_in[5];
    float* out = (float*)d_out;

    dim3 fgrid(NTOK / 256, 3);
    features_kernel<<<fgrid, 256>>>(x, phi_q, phi_k, phi_v);

    dim3 grid(SN / QPC, KSPLIT, BN);
    attn_partial_kernel<<<grid, NTHR>>>();

    finalize_kernel<<<NTOK / 256, 256>>>(W, bias, out);
}

// round 6
// speedup vs baseline: 1.0939x; 1.0939x over previous
#include <cuda_runtime.h>

#define BN 8
#define SN 2048
#define EN 8
#define NTOK (BN*SN)
#define KSPLIT 16
#define KCHUNK (SN/KSPLIT)   /* 128 keys per split == one smem tile */
#define TK 128               /* keys per smem tile (64 key-pairs) */
#define NTHR 128             /* threads per CTA; each thread owns 2 queries */
#define QPC 256              /* queries per CTA */
#define LOG2E 1.4426950408889634f

typedef unsigned long long u64;

/* Scratch (allocation-free rule: device globals) */
__device__ float g_Qf[NTOK * 8];                    /* [tok][Fa0..3*log2e, Fb0..3] */
__device__ float g_Kf[NTOK * 8];                    /* pair-interleaved: [tok/2][comp][2] */
__device__ float g_V [NTOK * 8];                    /* pair-interleaved: [tok/2][comp][2] */
__device__ float g_den[NTOK * KSPLIT];
__device__ float g_num[(size_t)NTOK * KSPLIT * 8];

/* ---- packed f32x2 helpers (Blackwell FFMA2 via PTX) ---- */
__device__ __forceinline__ u64 fma2(u64 a, u64 b, u64 c) {
    u64 d;
    asm("fma.rn.f32x2 %0, %1, %2, %3;" : "=l"(d) : "l"(a), "l"(b), "l"(c));
    return d;
}
__device__ __forceinline__ u64 mul2(u64 a, u64 b) {
    u64 d;
    asm("mul.rn.f32x2 %0, %1, %2;" : "=l"(d) : "l"(a), "l"(b));
    return d;
}
__device__ __forceinline__ u64 add2(u64 a, u64 b) {
    u64 d;
    asm("add.rn.f32x2 %0, %1, %2;" : "=l"(d) : "l"(a), "l"(b));
    return d;
}
__device__ __forceinline__ float2 unpack2(u64 d) {
    float2 r;
    asm("mov.b64 {%0, %1}, %2;" : "=f"(r.x), "=f"(r.y) : "l"(d));
    return r;
}
__device__ __forceinline__ u64 pack2(float lo, float hi) {
    u64 d;
    asm("mov.b64 %0, {%1, %2};" : "=l"(d) : "f"(lo), "f"(hi));
    return d;
}
__device__ __forceinline__ u64 pack_dup(float e) {
    u64 d;
    asm("mov.b64 %0, {%1, %1};" : "=l"(d) : "f"(e));
    return d;
}
__device__ __forceinline__ float ex2(float x) {
    float y;
    asm("ex2.approx.ftz.f32 %0, %1;" : "=f"(y) : "f"(x));
    return y;
}

/* ---------------- Kernel 1: per-token features ----------------
 * blockIdx.y = {0:Q, 1:K, 2:V}.
 * qlayer(x, phi)_w = prod_{u<=w} cos(x_u+phi_u)  (w>=1),
 * qlayer_0 = prod_{u=1..7} cos(x_u+phi_u).
 * Factorized similarity: sim = (Fa_q.Fa_k)*(Fb_q.Fb_k).
 */
__device__ __forceinline__ void qk_features(const float xv[8], const float* __restrict__ ph,
                                            float Fa[4], float Fb[4]) {
    float c[8];
#pragma unroll
    for (int u = 0; u < 8; u++) c[u] = __cosf(xv[u] + __ldg(&ph[u]));
    float q1 = c[0] * c[1];
    float q2 = q1 * c[2];
    float q3 = q2 * c[3];
    float q0 = c[1] * c[2] * c[3] * c[4] * c[5] * c[6] * c[7];
    float s0, s1, s2, s3, a0, a1, a2, a3;
    __sincosf(0.5f * q0, &s0, &a0);
    __sincosf(0.5f * q1, &s1, &a1);
    __sincosf(0.5f * q2, &s2, &a2);
    __sincosf(0.5f * q3, &s3, &a3);
    Fa[0] = a0 * a1; Fa[1] = s0 * a1; Fa[2] = a0 * s1; Fa[3] = s0 * s1;
    Fb[0] = a2 * a3; Fb[1] = s2 * a3; Fb[2] = a2 * s3; Fb[3] = s2 * s3;
}

__global__ void features_kernel(const float* __restrict__ x,
                                const float* __restrict__ phi_q,
                                const float* __restrict__ phi_k,
                                const float* __restrict__ phi_v) {
    int t = blockIdx.x * blockDim.x + threadIdx.x;
    if (t >= NTOK) return;
    const int kind = blockIdx.y;

    float xv[8];
    const float4* xp = reinterpret_cast<const float4*>(x + (size_t)t * 8);
    float4 xa = xp[0], xb = xp[1];
    xv[0] = xa.x; xv[1] = xa.y; xv[2] = xa.z; xv[3] = xa.w;
    xv[4] = xb.x; xv[5] = xb.y; xv[6] = xb.z; xv[7] = xb.w;

    if (kind == 0) {
        /* Q features: contiguous per token, Fa prescaled by log2e */
        float Fa[4], Fb[4];
        qk_features(xv, phi_q, Fa, Fb);
        float4* qo = reinterpret_cast<float4*>(g_Qf + (size_t)t * 8);
        qo[0] = make_float4(Fa[0] * LOG2E, Fa[1] * LOG2E, Fa[2] * LOG2E, Fa[3] * LOG2E);
        qo[1] = make_float4(Fb[0], Fb[1], Fb[2], Fb[3]);
    } else if (kind == 1) {
        /* K features: pair-interleaved layout [tok/2][comp][2] */
        float Fa[4], Fb[4];
        qk_features(xv, phi_k, Fa, Fb);
        float* ko = g_Kf + (size_t)(t & ~1) * 8 + (t & 1);
#pragma unroll
        for (int ccc = 0; ccc < 4; ccc++) ko[ccc * 2] = Fa[ccc];
#pragma unroll
        for (int ccc = 0; ccc < 4; ccc++) ko[(4 + ccc) * 2] = Fb[ccc];
    } else {
        /* V: all 8 qlayer outputs, pair-interleaved layout */
        float c[8];
#pragma unroll
        for (int u = 0; u < 8; u++) c[u] = __cosf(xv[u] + __ldg(&phi_v[u]));
        float v[8];
        v[1] = c[0] * c[1];
#pragma unroll
        for (int w = 2; w < 8; w++) v[w] = v[w - 1] * c[w];
        v[0] = c[1] * c[2] * c[3] * c[4] * c[5] * c[6] * c[7];
        float* vo = g_V + (size_t)(t & ~1) * 8 + (t & 1);
#pragma unroll
        for (int ccc = 0; ccc < 8; ccc++) vo[ccc * 2] = v[ccc];
    }
}

/* ---------------- Kernel 2: fused attention partials ----------------
 * sim(i,j) = |(Fa_qi.Fa_kj)(Fb_qi.Fb_kj)| in [0,1] -> softmax w/o max-sub.
 * Packed f32x2 over KEY PAIRS; K/V fetched via LDS.128 broadcasts
 * (4+4 per key-pair instead of 16 LDS.64 -> halves LSU time).
 * Each thread owns two query rows; one 128-key chunk per CTA (KSPLIT=16).
 */
__global__ __launch_bounds__(NTHR) void attn_partial_kernel() {
    __shared__ ulonglong2 sK[TK / 2 * 4];   /* 64 key-pairs x 8 packed comps = 4KB */
    __shared__ ulonglong2 sV[TK / 2 * 4];   /* 64 key-pairs x 8 packed comps = 4KB */

    const int b  = blockIdx.z;
    const int ks = blockIdx.y;
    const int qA = blockIdx.x * QPC + threadIdx.x;   /* query A */
    const int qB = qA + NTHR;                        /* query B */

    /* fill the single K/V tile */
    {
        const int kbase = b * SN + ks * KCHUNK;
        const ulonglong2* kg2 = reinterpret_cast<const ulonglong2*>(g_Kf + (size_t)kbase * 8);
        const ulonglong2* vg2 = reinterpret_cast<const ulonglong2*>(g_V  + (size_t)kbase * 8);
#pragma unroll
        for (int i = 0; i < 2; i++) sK[threadIdx.x + i * NTHR] = kg2[threadIdx.x + i * NTHR];
#pragma unroll
        for (int i = 0; i < 2; i++) sV[threadIdx.x + i * NTHR] = vg2[threadIdx.x + i * NTHR];
    }

    /* Query features, each component dup'd into both f32x2 lanes */
    u64 qa[8], qb[8];
    {
        const float* pa = g_Qf + (size_t)(b * SN + qA) * 8;
        const float* pb = g_Qf + (size_t)(b * SN + qB) * 8;
#pragma unroll
        for (int i = 0; i < 8; i++) {
            qa[i] = pack_dup(pa[i]);
            qb[i] = pack_dup(pb[i]);
        }
    }

    u64 denA = 0ull, denB = 0ull;
    u64 accA[8], accB[8];
#pragma unroll
    for (int i = 0; i < 8; i++) { accA[i] = 0ull; accB[i] = 0ull; }

    __syncthreads();

#pragma unroll 4
    for (int jp = 0; jp < TK / 2; jp++) {
        /* 4 LDS.128 broadcasts for K comps, 4 for V comps */
        const ulonglong2 K01 = sK[jp * 4 + 0];
        const ulonglong2 K23 = sK[jp * 4 + 1];
        const ulonglong2 K45 = sK[jp * 4 + 2];
        const ulonglong2 K67 = sK[jp * 4 + 3];

        /* factorized dot for both key lanes, both queries */
        u64 daA = mul2(qa[0], K01.x);
        u64 daB = mul2(qb[0], K01.x);
        daA = fma2(qa[1], K01.y, daA);  daB = fma2(qb[1], K01.y, daB);
        daA = fma2(qa[2], K23.x, daA);  daB = fma2(qb[2], K23.x, daB);
        daA = fma2(qa[3], K23.y, daA);  daB = fma2(qb[3], K23.y, daB);
        u64 dbA = mul2(qa[4], K45.x);
        u64 dbB = mul2(qb[4], K45.x);
        dbA = fma2(qa[5], K45.y, dbA);  dbB = fma2(qb[5], K45.y, dbB);
        dbA = fma2(qa[6], K67.x, dbA);  dbB = fma2(qb[6], K67.x, dbB);
        dbA = fma2(qa[7], K67.y, dbA);  dbB = fma2(qb[7], K67.y, dbB);
        u64 dA = mul2(daA, dbA);     /* (log2e*simA_k0, log2e*simA_k1) signed */
        u64 dB = mul2(daB, dbB);

        float2 uA = unpack2(dA);
        float2 uB = unpack2(dB);
        u64 eA2 = pack2(ex2(fabsf(uA.x)), ex2(fabsf(uA.y)));
        u64 eB2 = pack2(ex2(fabsf(uB.x)), ex2(fabsf(uB.y)));
        denA = add2(denA, eA2);
        denB = add2(denB, eB2);

        const ulonglong2 V01 = sV[jp * 4 + 0];
        const ulonglong2 V23 = sV[jp * 4 + 1];
        const ulonglong2 V45 = sV[jp * 4 + 2];
        const ulonglong2 V67 = sV[jp * 4 + 3];
        accA[0] = fma2(eA2, V01.x, accA[0]);  accB[0] = fma2(eB2, V01.x, accB[0]);
        accA[1] = fma2(eA2, V01.y, accA[1]);  accB[1] = fma2(eB2, V01.y, accB[1]);
        accA[2] = fma2(eA2, V23.x, accA[2]);  accB[2] = fma2(eB2, V23.x, accB[2]);
        accA[3] = fma2(eA2, V23.y, accA[3]);  accB[3] = fma2(eB2, V23.y, accB[3]);
        accA[4] = fma2(eA2, V45.x, accA[4]);  accB[4] = fma2(eB2, V45.x, accB[4]);
        accA[5] = fma2(eA2, V45.y, accA[5]);  accB[5] = fma2(eB2, V45.y, accB[5]);
        accA[6] = fma2(eA2, V67.x, accA[6]);  accB[6] = fma2(eB2, V67.x, accB[6]);
        accA[7] = fma2(eA2, V67.y, accA[7]);  accB[7] = fma2(eB2, V67.y, accB[7]);
    }

    /* horizontal-add packed lanes, write partials */
    {
        float2 dA = unpack2(denA);
        float2 dB = unpack2(denB);
        g_den[(size_t)(b * SN + qA) * KSPLIT + ks] = dA.x + dA.y;
        g_den[(size_t)(b * SN + qB) * KSPLIT + ks] = dB.x + dB.y;
        float na[8], nb[8];
#pragma unroll
        for (int ccc = 0; ccc < 8; ccc++) {
            float2 a = unpack2(accA[ccc]);
            float2 bb = unpack2(accB[ccc]);
            na[ccc] = a.x + a.y;
            nb[ccc] = bb.x + bb.y;
        }
        float4* oa = reinterpret_cast<float4*>(g_num + ((size_t)(b * SN + qA) * KSPLIT + ks) * 8);
        float4* ob = reinterpret_cast<float4*>(g_num + ((size_t)(b * SN + qB) * KSPLIT + ks) * 8);
        oa[0] = make_float4(na[0], na[1], na[2], na[3]);
        oa[1] = make_float4(na[4], na[5], na[6], na[7]);
        ob[0] = make_float4(nb[0], nb[1], nb[2], nb[3]);
        ob[1] = make_float4(nb[4], nb[5], nb[6], nb[7]);
    }
}

/* ---------------- Kernel 3: combine splits + output projection ---------------- */
__global__ void finalize_kernel(const float* __restrict__ W,
                                const float* __restrict__ bias,
                                float* __restrict__ out) {
    int t = blockIdx.x * blockDim.x + threadIdx.x;
    if (t >= NTOK) return;

    float den = 0.f, num[8];
#pragma unroll
    for (int e = 0; e < 8; e++) num[e] = 0.f;
#pragma unroll
    for (int ks = 0; ks < KSPLIT; ks++) {
        den += g_den[(size_t)t * KSPLIT + ks];
        const float4* p = reinterpret_cast<const float4*>(g_num + ((size_t)t * KSPLIT + ks) * 8);
        float4 p0 = p[0], p1 = p[1];
        num[0] += p0.x; num[1] += p0.y; num[2] += p0.z; num[3] += p0.w;
        num[4] += p1.x; num[5] += p1.y; num[6] += p1.z; num[7] += p1.w;
    }
    float inv = 1.0f / den;
    float o[8];
#pragma unroll
    for (int e = 0; e < 8; e++) o[e] = num[e] * inv;

#pragma unroll
    for (int d = 0; d < 8; d++) {
        float y = __ldg(&bias[d]);
#pragma unroll
        for (int e = 0; e < 8; e++) y += o[e] * __ldg(&W[d * 8 + e]);
        out[t * 8 + d] = y;
    }
}

extern "C" void kernel_launch(void* const* d_in, const int* in_sizes, int n_in,
                              void* d_out, int out_size) {
    const float* x     = (const float*)d_in[0];
    const float* phi_q = (const float*)d_in[1];
    const float* phi_k = (const float*)d_in[2];
    const float* phi_v = (const float*)d_in[3];
    const float* W     = (const float*)d_in[4];
    const float* bias  = (const float*)d_in[5];
    float* out = (float*)d_out;

    dim3 fgrid(NTOK / 128, 3);
    features_kernel<<<fgrid, 128>>>(x, phi_q, phi_k, phi_v);

    dim3 grid(SN / QPC, KSPLIT, BN);
    attn_partial_kernel<<<grid, NTHR>>>();

    finalize_kernel<<<NTOK / 256, 256>>>(W, bias, out);
}